// round 3
// baseline (speedup 1.0000x reference)
#include <cuda_runtime.h>
#include <cuda_bf16.h>

// Elementwise fused: out = (x + 2) + (x * 3) - (x - 1) * (x / 2)
// 8192 x 16384 fp32 = 134217728 elements = 33554432 float4s.
// Streaming at HBM roofline: 8 front-batched LDG.128 per thread (MLP=8),
// evict-first cache hints, exact grid tiling (no tail, no bounds checks in
// the hot path when the grid tiles n4 exactly).

__device__ __forceinline__ float fuse1(float v) {
    return (v + 2.0f) + (v * 3.0f) - (v - 1.0f) * (v * 0.5f);
}

__device__ __forceinline__ float4 fuse4(float4 v) {
    float4 r;
    r.x = fuse1(v.x);
    r.y = fuse1(v.y);
    r.z = fuse1(v.z);
    r.w = fuse1(v.w);
    return r;
}

template <int UNROLL>
__global__ void fused_elemwise_kernel(const float4* __restrict__ x,
                                      float4* __restrict__ out,
                                      int n4) {
    int stride = gridDim.x * blockDim.x;
    int base = blockIdx.x * blockDim.x + threadIdx.x;

    int last = base + (UNROLL - 1) * stride;
    if (last < n4) {
        float4 v[UNROLL];
#pragma unroll
        for (int k = 0; k < UNROLL; k++)
            v[k] = __ldcs(&x[base + k * stride]);   // front-batched, MLP=UNROLL
#pragma unroll
        for (int k = 0; k < UNROLL; k++)
            __stcs(&out[base + k * stride], fuse4(v[k]));
    } else {
        for (int i = base; i < n4; i += stride)
            __stcs(&out[i], fuse4(__ldcs(&x[i])));
    }
}

__global__ void fused_elemwise_tail(const float* __restrict__ x,
                                    float* __restrict__ out,
                                    int start, int n) {
    int i = start + blockIdx.x * blockDim.x + threadIdx.x;
    if (i < n) out[i] = fuse1(x[i]);
}

extern "C" void kernel_launch(void* const* d_in, const int* in_sizes, int n_in,
                              void* d_out, int out_size) {
    const float* x = (const float*)d_in[0];
    float* out = (float*)d_out;
    int n = in_sizes[0];

    int n4 = n / 4;
    if (n4 > 0) {
        constexpr int UNROLL = 8;
        const int threads = 256;
        int total_threads = (n4 + UNROLL - 1) / UNROLL;
        int blocks = (total_threads + threads - 1) / threads;
        fused_elemwise_kernel<UNROLL><<<blocks, threads>>>(
            (const float4*)x, (float4*)out, n4);
    }
    int rem = n - n4 * 4;
    if (rem > 0) {
        fused_elemwise_tail<<<1, 256>>>(x, out, n4 * 4, n);
    }
}

// round 4
// speedup vs baseline: 1.0002x; 1.0002x over previous
#include <cuda_runtime.h>
#include <cuda_bf16.h>

// Elementwise fused: out = (x + 2) + (x * 3) - (x - 1) * (x / 2)
//                       == -0.5*x^2 + 4.5*x + 2  (2 FFMAs per element)
// 8192 x 16384 fp32 = 134217728 elements = 33554432 float4s.
// Block-contiguous tiling: each CTA owns a contiguous 64KB chunk (1-2 TLB
// pages), thread loads stride 4KB. 8 front-batched LDG.128 per thread,
// evict-first cache hints.

__device__ __forceinline__ float fuse1(float v) {
    return fmaf(v, fmaf(-0.5f, v, 4.5f), 2.0f);
}

__device__ __forceinline__ float4 fuse4(float4 v) {
    float4 r;
    r.x = fuse1(v.x);
    r.y = fuse1(v.y);
    r.z = fuse1(v.z);
    r.w = fuse1(v.w);
    return r;
}

template <int UNROLL, int THREADS>
__global__ void fused_elemwise_kernel(const float4* __restrict__ x,
                                      float4* __restrict__ out,
                                      int n4) {
    // Each CTA covers a contiguous chunk of THREADS*UNROLL float4s.
    int base = blockIdx.x * (THREADS * UNROLL) + threadIdx.x;

    if (base + (UNROLL - 1) * THREADS < n4) {
        float4 v[UNROLL];
#pragma unroll
        for (int k = 0; k < UNROLL; k++)
            v[k] = __ldcs(&x[base + k * THREADS]);   // front-batched, MLP=UNROLL
#pragma unroll
        for (int k = 0; k < UNROLL; k++)
            __stcs(&out[base + k * THREADS], fuse4(v[k]));
    } else {
#pragma unroll
        for (int k = 0; k < UNROLL; k++) {
            int i = base + k * THREADS;
            if (i < n4) __stcs(&out[i], fuse4(__ldcs(&x[i])));
        }
    }
}

__global__ void fused_elemwise_tail(const float* __restrict__ x,
                                    float* __restrict__ out,
                                    int start, int n) {
    int i = start + blockIdx.x * blockDim.x + threadIdx.x;
    if (i < n) out[i] = fuse1(x[i]);
}

extern "C" void kernel_launch(void* const* d_in, const int* in_sizes, int n_in,
                              void* d_out, int out_size) {
    const float* x = (const float*)d_in[0];
    float* out = (float*)d_out;
    int n = in_sizes[0];

    int n4 = n / 4;
    if (n4 > 0) {
        constexpr int UNROLL = 8;
        constexpr int THREADS = 256;
        int per_cta = THREADS * UNROLL;
        int blocks = (n4 + per_cta - 1) / per_cta;
        fused_elemwise_kernel<UNROLL, THREADS><<<blocks, THREADS>>>(
            (const float4*)x, (float4*)out, n4);
    }
    int rem = n - n4 * 4;
    if (rem > 0) {
        fused_elemwise_tail<<<1, 256>>>(x, out, n4 * 4, n);
    }
}